// round 4
// baseline (speedup 1.0000x reference)
#include <cuda_runtime.h>
#include <math_constants.h>

#define NB 64
#define NM 1024
#define NN (NB*NM)      // 65536 nodes
#define NH 64
#define NK 16
#define HPAD 20         // padded k-stride for transposed hidden tile

// ---------------- device scratch (static globals; no allocation) -------------
__device__ float g_h0[NN*NH];
__device__ float g_h1[NN*NH];
__device__ float g_a [NN*NH];
__device__ float g_e [NN*NH];
__device__ float g_sq[NN];
__device__ int   g_idx[NN*NK];

// ---------------- encoder: x[4] -> 32 -> 64 (ReLU both), + sqnorm ------------
__global__ void __launch_bounds__(256) enc_kernel(
    const float* __restrict__ x,
    const float* __restrict__ w1, const float* __restrict__ b1,
    const float* __restrict__ w2, const float* __restrict__ b2)
{
    __shared__ float w1s[4*32];
    __shared__ float b1s[32];
    __shared__ float w2s[32*64];
    __shared__ float b2s[64];
    int tid = threadIdx.x;
    if (tid < 128) w1s[tid] = w1[tid];
    if (tid < 32)  b1s[tid] = b1[tid];
    for (int q = tid; q < 32*64; q += 256) w2s[q] = w2[q];
    if (tid < 64)  b2s[tid] = b2[tid];
    __syncthreads();

    int n = blockIdx.x * 256 + tid;
    float4 xv = reinterpret_cast<const float4*>(x)[n];

    float hid[32];
#pragma unroll
    for (int o = 0; o < 32; o++) {
        float acc = b1s[o];
        acc += xv.x * w1s[o];
        acc += xv.y * w1s[32 + o];
        acc += xv.z * w1s[64 + o];
        acc += xv.w * w1s[96 + o];
        hid[o] = fmaxf(acc, 0.f);
    }

    float sq = 0.f;
    float4* outp = reinterpret_cast<float4*>(&g_h0[(size_t)n * NH]);
    const float4* w2v = reinterpret_cast<const float4*>(w2s);
    const float4* b2v = reinterpret_cast<const float4*>(b2s);
#pragma unroll
    for (int og = 0; og < 16; og++) {
        float4 acc = b2v[og];
#pragma unroll
        for (int j = 0; j < 32; j++) {
            float hv = hid[j];
            float4 wv = w2v[j*16 + og];
            acc.x += hv * wv.x; acc.y += hv * wv.y;
            acc.z += hv * wv.z; acc.w += hv * wv.w;
        }
        acc.x = fmaxf(acc.x, 0.f); acc.y = fmaxf(acc.y, 0.f);
        acc.z = fmaxf(acc.z, 0.f); acc.w = fmaxf(acc.w, 0.f);
        sq += acc.x*acc.x + acc.y*acc.y + acc.z*acc.z + acc.w*acc.w;
        outp[og] = acc;
    }
    g_sq[n] = sq;
}

// ---------------- kNN: per row, top-16 smallest (sq_j - 2*dot) ---------------
// block = 128 threads = 128 rows of one batch; 8 blocks per batch.
__global__ void __launch_bounds__(128) knn_kernel(const float* __restrict__ h)
{
    __shared__ float hs[32*NH];
    __shared__ float sqs[32];

    int b  = blockIdx.x >> 3;
    int il = (blockIdx.x & 7) * 128 + threadIdx.x;   // local row index
    int i  = b * NM + il;

    float hi[NH];
    {
        const float4* src = reinterpret_cast<const float4*>(h + (size_t)i * NH);
#pragma unroll
        for (int f = 0; f < 16; f++) {
            float4 v = src[f];
            hi[f*4+0] = v.x; hi[f*4+1] = v.y; hi[f*4+2] = v.z; hi[f*4+3] = v.w;
        }
    }

    float dist[NK]; int idx[NK];
#pragma unroll
    for (int k = 0; k < NK; k++) { dist[k] = CUDART_INF_F; idx[k] = 0; }
    float worst = CUDART_INF_F; int wpos = 0;

    for (int jt = 0; jt < NM; jt += 32) {
        __syncthreads();
        {
            const float4* src = reinterpret_cast<const float4*>(h + (size_t)(b*NM + jt) * NH);
            float4* dst = reinterpret_cast<float4*>(hs);
#pragma unroll
            for (int it = 0; it < 4; it++) dst[threadIdx.x + 128*it] = src[threadIdx.x + 128*it];
            if (threadIdx.x < 32) sqs[threadIdx.x] = g_sq[b*NM + jt + threadIdx.x];
        }
        __syncthreads();

#pragma unroll 4
        for (int c = 0; c < 32; c++) {
            const float4* hv = reinterpret_cast<const float4*>(hs + c*NH);
            float d0 = 0.f, d1 = 0.f, d2 = 0.f, d3 = 0.f;
#pragma unroll
            for (int f = 0; f < 16; f++) {
                float4 v = hv[f];
                d0 += hi[f*4+0] * v.x;
                d1 += hi[f*4+1] * v.y;
                d2 += hi[f*4+2] * v.z;
                d3 += hi[f*4+3] * v.w;
            }
            float dot = (d0 + d1) + (d2 + d3);
            float d = sqs[c] - 2.f * dot;
            int j = jt + c;
            if (d < worst && j != il) {
#pragma unroll
                for (int k = 0; k < NK; k++) if (k == wpos) { dist[k] = d; idx[k] = j; }
                worst = dist[0]; wpos = 0;
#pragma unroll
                for (int k = 1; k < NK; k++) if (dist[k] > worst) { worst = dist[k]; wpos = k; }
            }
        }
    }
#pragma unroll
    for (int k = 0; k < NK; k++) g_idx[(size_t)i*NK + k] = b*NM + idx[k];
}

// ---------------- prep: a = h@W1[:64] + b1,  e = h@W1[64:] -------------------
__global__ void __launch_bounds__(256) prep_kernel(
    const float* __restrict__ h,
    const float* __restrict__ w1, const float* __restrict__ b1)
{
    __shared__ float w1s[128*64];
    __shared__ float b1s[64];
    for (int q = threadIdx.x; q < 128*64; q += 256) w1s[q] = w1[q];
    if (threadIdx.x < 64) b1s[threadIdx.x] = b1[threadIdx.x];
    __syncthreads();

    int n = blockIdx.x * 256 + threadIdx.x;
    float hv[NH];
    {
        const float4* src = reinterpret_cast<const float4*>(h + (size_t)n * NH);
#pragma unroll
        for (int f = 0; f < 16; f++) {
            float4 v = src[f];
            hv[f*4+0] = v.x; hv[f*4+1] = v.y; hv[f*4+2] = v.z; hv[f*4+3] = v.w;
        }
    }

    const float4* wA = reinterpret_cast<const float4*>(w1s);            // rows 0..63
    const float4* wB = reinterpret_cast<const float4*>(w1s + 64*64);    // rows 64..127
    const float4* b1v = reinterpret_cast<const float4*>(b1s);
    float4* ap = reinterpret_cast<float4*>(&g_a[(size_t)n * NH]);
    float4* ep = reinterpret_cast<float4*>(&g_e[(size_t)n * NH]);

#pragma unroll 2
    for (int og = 0; og < 16; og++) {
        float4 acc = b1v[og];
#pragma unroll 8
        for (int f = 0; f < 64; f++) {
            float x = hv[f];
            float4 wv = wA[f*16 + og];
            acc.x += x*wv.x; acc.y += x*wv.y; acc.z += x*wv.z; acc.w += x*wv.w;
        }
        ap[og] = acc;
    }
#pragma unroll 2
    for (int og = 0; og < 16; og++) {
        float4 acc = make_float4(0.f, 0.f, 0.f, 0.f);
#pragma unroll 8
        for (int f = 0; f < 64; f++) {
            float x = hv[f];
            float4 wv = wB[f*16 + og];
            acc.x += x*wv.x; acc.y += x*wv.y; acc.z += x*wv.z; acc.w += x*wv.w;
        }
        ep[og] = acc;
    }
}

// ---------------- msg: hidden = relu(a_i + e_j - e_i); out = max_k hidden@W2+b2
// block = 128 threads = 4 warps; warp handles one node.
__global__ void __launch_bounds__(128) msg_kernel(
    const float* __restrict__ w2, const float* __restrict__ b2,
    float* __restrict__ hout)
{
    __shared__ float w2s[64*64];
    __shared__ float hidden[4][64*HPAD];     // [warp][o*HPAD + k]
    for (int q = threadIdx.x; q < 64*64; q += 128) w2s[q] = w2[q];
    __syncthreads();

    int warp = threadIdx.x >> 5;
    int l    = threadIdx.x & 31;
    int i    = blockIdx.x * 4 + warp;

    float a0 = g_a[(size_t)i*NH + l],      a1 = g_a[(size_t)i*NH + 32 + l];
    float e0 = g_e[(size_t)i*NH + l],      e1 = g_e[(size_t)i*NH + 32 + l];
    int jreg = (l < NK) ? g_idx[(size_t)i*NK + l] : 0;

    float* hid = hidden[warp];
#pragma unroll
    for (int k = 0; k < NK; k++) {
        int j = __shfl_sync(0xffffffffu, jreg, k);
        float ej0 = g_e[(size_t)j*NH + l];
        float ej1 = g_e[(size_t)j*NH + 32 + l];
        hid[l*HPAD + k]        = fmaxf(a0 + ej0 - e0, 0.f);
        hid[(l+32)*HPAD + k]   = fmaxf(a1 + ej1 - e1, 0.f);
    }
    __syncwarp();

    float accL[NK], accH[NK];
#pragma unroll
    for (int k = 0; k < NK; k++) { accL[k] = 0.f; accH[k] = 0.f; }

#pragma unroll 2
    for (int o = 0; o < 64; o++) {
        float wl = w2s[o*64 + l];
        float wh = w2s[o*64 + 32 + l];
        const float4* hp = reinterpret_cast<const float4*>(hid + o*HPAD);
        float4 h0v = hp[0], h1v = hp[1], h2v = hp[2], h3v = hp[3];
        float hk[16] = { h0v.x,h0v.y,h0v.z,h0v.w, h1v.x,h1v.y,h1v.z,h1v.w,
                         h2v.x,h2v.y,h2v.z,h2v.w, h3v.x,h3v.y,h3v.z,h3v.w };
#pragma unroll
        for (int k = 0; k < NK; k++) {
            accL[k] += hk[k] * wl;
            accH[k] += hk[k] * wh;
        }
    }

    float m0 = accL[0], m1 = accH[0];
#pragma unroll
    for (int k = 1; k < NK; k++) { m0 = fmaxf(m0, accL[k]); m1 = fmaxf(m1, accH[k]); }
    m0 += b2[l];
    m1 += b2[32 + l];

    hout[(size_t)i*NH + l]      = m0;
    hout[(size_t)i*NH + 32 + l] = m1;

    float s = m0*m0 + m1*m1;
#pragma unroll
    for (int off = 16; off; off >>= 1) s += __shfl_xor_sync(0xffffffffu, s, off);
    if (l == 0) g_sq[i] = s;
}

// ---------------- pool + output MLP -----------------------------------------
__global__ void __launch_bounds__(256) pool_kernel(
    const float* __restrict__ h,
    const float* __restrict__ w1, const float* __restrict__ b1,
    const float* __restrict__ w2, const float* __restrict__ b2,
    float* __restrict__ out)
{
    __shared__ float part[256];
    __shared__ float g[64];
    int b = blockIdx.x, tid = threadIdx.x;
    int c = tid & 63, rb = tid >> 6;
    float s = 0.f;
    for (int r = rb; r < NM; r += 4) s += h[(size_t)(b*NM + r)*NH + c];
    part[tid] = s;
    __syncthreads();
    if (tid < 64) g[tid] = (part[tid] + part[tid+64] + part[tid+128] + part[tid+192]) * (1.f/NM);
    __syncthreads();
    if (tid < 32) {
        float acc = b1[tid];
#pragma unroll 8
        for (int f = 0; f < 64; f++) acc += g[f] * w1[f*32 + tid];
        acc = fmaxf(acc, 0.f);
        acc *= w2[tid];
#pragma unroll
        for (int off = 16; off; off >>= 1) acc += __shfl_xor_sync(0xffffffffu, acc, off);
        if (tid == 0) out[b] = acc + b2[0];
    }
}

// ---------------- launch -----------------------------------------------------
extern "C" void kernel_launch(void* const* d_in, const int* in_sizes, int n_in,
                              void* d_out, int out_size)
{
    const float* x      = (const float*)d_in[0];
    const float* enc_w1 = (const float*)d_in[2];
    const float* enc_b1 = (const float*)d_in[3];
    const float* enc_w2 = (const float*)d_in[4];
    const float* enc_b2 = (const float*)d_in[5];
    const float* ec1_w1 = (const float*)d_in[6];
    const float* ec1_b1 = (const float*)d_in[7];
    const float* ec1_w2 = (const float*)d_in[8];
    const float* ec1_b2 = (const float*)d_in[9];
    const float* ec2_w1 = (const float*)d_in[10];
    const float* ec2_b1 = (const float*)d_in[11];
    const float* ec2_w2 = (const float*)d_in[12];
    const float* ec2_b2 = (const float*)d_in[13];
    const float* out_w1 = (const float*)d_in[14];
    const float* out_b1 = (const float*)d_in[15];
    const float* out_w2 = (const float*)d_in[16];
    const float* out_b2 = (const float*)d_in[17];
    float* out = (float*)d_out;

    float *h0, *h1;
    cudaGetSymbolAddress((void**)&h0, g_h0);
    cudaGetSymbolAddress((void**)&h1, g_h1);

    // encoder -> h0 (+ sqnorms)
    enc_kernel<<<NN/256, 256>>>(x, enc_w1, enc_b1, enc_w2, enc_b2);
    // EdgeConv 1
    knn_kernel<<<NB*8, 128>>>(h0);
    prep_kernel<<<NN/256, 256>>>(h0, ec1_w1, ec1_b1);
    msg_kernel<<<NN/4, 128>>>(ec1_w2, ec1_b2, h1);
    // EdgeConv 2
    knn_kernel<<<NB*8, 128>>>(h1);
    prep_kernel<<<NN/256, 256>>>(h1, ec2_w1, ec2_b1);
    msg_kernel<<<NN/4, 128>>>(ec2_w2, ec2_b2, h0);   // reuse h0 as h2
    // pool + output MLP
    pool_kernel<<<NB, 256>>>(h0, out_w1, out_b1, out_w2, out_b2, out);
}